// round 2
// baseline (speedup 1.0000x reference)
#include <cuda_runtime.h>
#include <math.h>
#include <stdint.h>

// Problem dims (fixed by the dataset generator)
#define B_  1024
#define F_  4096
#define V_  20000
#define E_  512
#define H_  1024
#define L_  20
#define D_  4
#define G4H 4096   // 4*H

// ---------------- scratch (no allocations allowed) ----------------
__device__ float g_h[B_*H_];
__device__ float g_c[B_*H_];
__device__ float g_gates[(size_t)B_*G4H];
__device__ float g_w[B_*E_];
__device__ float g_logits[(size_t)B_*V_];
__device__ int   g_msg[L_*B_];
__device__ float g_logprob[B_];
__device__ float g_bias_s[G4H];
__device__ float g_bias_r[G4H];
__device__ float g_r[(size_t)B_*F_];
__device__ float g_ts[(size_t)B_*B_];
__device__ float g_ds[(size_t)D_*B_*B_];
__device__ float g_lsum[B_];
__device__ float g_tp[B_];
__device__ float g_dp[D_*B_];

// ---------------- GEMM: C[M,N] (+)= A[M,K] @ B[N,K]^T (+ bias[N]) ----------------
// A row-major [M,K], Bm row-major [N,K] (both K-contiguous -> "NT" gemm).
// M must be a multiple of 128 (always 1024 here). N may have a tail. K % 16 == 0.
#define BM 128
#define BN 128
#define BKK 16

template<bool ACC, bool BIAS>
__global__ __launch_bounds__(256, 2)
void gemm_nt(const float* __restrict__ A, const float* __restrict__ Bm,
             const float* __restrict__ bias, float* __restrict__ C,
             int M, int N, int K)
{
    __shared__ float As[BKK][BM + 4];
    __shared__ float Bs[BKK][BN + 4];

    const int tid = threadIdx.x;
    const int tx = tid & 15;       // 0..15  -> N direction
    const int ty = tid >> 4;       // 0..15  -> M direction
    const int bm = blockIdx.y * BM;
    const int bn = blockIdx.x * BN;

    const int lrow = tid >> 2;         // 0..63
    const int lk4  = (tid & 3) * 4;    // 0,4,8,12

    float acc[8][8];
#pragma unroll
    for (int i = 0; i < 8; i++)
#pragma unroll
        for (int j = 0; j < 8; j++) acc[i][j] = 0.0f;

    for (int kt = 0; kt < K; kt += BKK) {
        // load A tile (M always in range)
#pragma unroll
        for (int r = 0; r < 2; r++) {
            int row = lrow + r * 64;
            float4 v = *(const float4*)&A[(size_t)(bm + row) * K + kt + lk4];
            As[lk4 + 0][row] = v.x; As[lk4 + 1][row] = v.y;
            As[lk4 + 2][row] = v.z; As[lk4 + 3][row] = v.w;
        }
        // load B tile (guard N tail)
#pragma unroll
        for (int r = 0; r < 2; r++) {
            int row = lrow + r * 64;
            int nrow = bn + row;
            float4 v = make_float4(0.f, 0.f, 0.f, 0.f);
            if (nrow < N) v = *(const float4*)&Bm[(size_t)nrow * K + kt + lk4];
            Bs[lk4 + 0][row] = v.x; Bs[lk4 + 1][row] = v.y;
            Bs[lk4 + 2][row] = v.z; Bs[lk4 + 3][row] = v.w;
        }
        __syncthreads();

#pragma unroll
        for (int k = 0; k < BKK; k++) {
            float a[8], b[8];
            *(float4*)&a[0] = *(const float4*)&As[k][ty * 8];
            *(float4*)&a[4] = *(const float4*)&As[k][ty * 8 + 4];
            *(float4*)&b[0] = *(const float4*)&Bs[k][tx * 8];
            *(float4*)&b[4] = *(const float4*)&Bs[k][tx * 8 + 4];
#pragma unroll
            for (int i = 0; i < 8; i++)
#pragma unroll
                for (int j = 0; j < 8; j++)
                    acc[i][j] = fmaf(a[i], b[j], acc[i][j]);
        }
        __syncthreads();
    }

    // epilogue
#pragma unroll
    for (int i = 0; i < 8; i++) {
        int m = bm + ty * 8 + i;
#pragma unroll
        for (int j = 0; j < 8; j++) {
            int n = bn + tx * 8 + j;
            if (n < N) {
                float v = acc[i][j];
                if (BIAS) v += bias[n];
                size_t off = (size_t)m * N + n;
                if (ACC) v += C[off];
                C[off] = v;
            }
        }
    }
}

// ---------------- small kernels ----------------
__global__ void zero_kernel(float* p, int n) {
    int i = blockIdx.x * blockDim.x + threadIdx.x;
    if (i < n) p[i] = 0.0f;
}

__global__ void add_vec(const float* a, const float* b, float* o, int n) {
    int i = blockIdx.x * blockDim.x + threadIdx.x;
    if (i < n) o[i] = a[i] + b[i];
}

// broadcast emb[*startp] to all rows
__global__ void gather_start(const float* __restrict__ emb, const int* __restrict__ startp,
                             float* __restrict__ out) {
    int s = *startp;
    int b = blockIdx.x;
    int e = threadIdx.x;  // 128 threads, E_/4 = 128 float4
    ((float4*)out)[(size_t)b * (E_ / 4) + e] =
        ((const float4*)emb)[(size_t)s * (E_ / 4) + e];
}

__global__ void gather_tok(const float* __restrict__ emb, const int* __restrict__ tok,
                           float* __restrict__ out) {
    int b = blockIdx.x;
    int t = tok[b];
    int e = threadIdx.x;
    ((float4*)out)[(size_t)b * (E_ / 4) + e] =
        ((const float4*)emb)[(size_t)t * (E_ / 4) + e];
}

__device__ __forceinline__ float sigf(float x) { return 1.0f / (1.0f + expf(-x)); }

// gates layout [B, 4H] chunks: i, f, g, o
__global__ void lstm_cell(const float* __restrict__ gates,
                          float* __restrict__ h, float* __restrict__ c) {
    int idx = blockIdx.x * blockDim.x + threadIdx.x;
    if (idx >= B_ * H_) return;
    int b = idx >> 10;            // /H_
    int j = idx & (H_ - 1);
    size_t base = (size_t)b * G4H;
    float gi = gates[base + j];
    float gf = gates[base + H_ + j];
    float gg = gates[base + 2 * H_ + j];
    float go = gates[base + 3 * H_ + j];
    float cn = sigf(gf) * c[idx] + sigf(gi) * tanhf(gg);
    c[idx] = cn;
    h[idx] = sigf(go) * tanhf(cn);
}

// per-row argmax over V (lowest index on ties = JAX semantics);
// if writeLp: logprob[b] = logits[amax] - logsumexp = -log(sum exp(x - max))
__global__ void argmax_row(const float* __restrict__ logits, int* __restrict__ msg,
                           float* __restrict__ logprob, int writeLp) {
    int b = blockIdx.x;
    const float* row = logits + (size_t)b * V_;
    int tid = threadIdx.x;

    float best = -3.4e38f;
    int bi = 0x7fffffff;
    for (int v = tid; v < V_; v += 256) {
        float x = row[v];
        if (x > best) { best = x; bi = v; }
    }
    __shared__ float sv[256];
    __shared__ int   si[256];
    sv[tid] = best; si[tid] = bi;
    __syncthreads();
    for (int s = 128; s > 0; s >>= 1) {
        if (tid < s) {
            if (sv[tid + s] > sv[tid] ||
                (sv[tid + s] == sv[tid] && si[tid + s] < si[tid])) {
                sv[tid] = sv[tid + s]; si[tid] = si[tid + s];
            }
        }
        __syncthreads();
    }
    float m = sv[0];
    int amax = si[0];
    if (tid == 0) msg[b] = amax;

    if (writeLp) {
        __syncthreads();
        float s = 0.0f;
        for (int v = tid; v < V_; v += 256) s += expf(row[v] - m);
        sv[tid] = s;
        __syncthreads();
        for (int st = 128; st > 0; st >>= 1) {
            if (tid < st) sv[tid] += sv[tid + st];
            __syncthreads();
        }
        if (tid == 0) logprob[b] = -logf(sv[0]);
    }
}

// per-row-b reductions over k: hinge*logprob sum, exp(ts) sum, exp(ds[d]) sums
__global__ void reduce_rows(const float* __restrict__ ts, const float* __restrict__ ds,
                            const float* __restrict__ lp,
                            float* __restrict__ lsum, float* __restrict__ tp,
                            float* __restrict__ dp) {
    int b = blockIdx.x;
    int tid = threadIdx.x;
    float l = 0.f, t = 0.f, d0 = 0.f, d1 = 0.f, d2 = 0.f, d3 = 0.f;
    for (int k = tid; k < B_; k += 256) {
        float tv = ts[(size_t)b * B_ + k];
        float v0 = ds[(size_t)0 * B_ * B_ + (size_t)b * B_ + k];
        float v1 = ds[(size_t)1 * B_ * B_ + (size_t)b * B_ + k];
        float v2 = ds[(size_t)2 * B_ * B_ + (size_t)b * B_ + k];
        float v3 = ds[(size_t)3 * B_ * B_ + (size_t)b * B_ + k];
        float h = fmaxf(0.f, 1.f - tv + v0) + fmaxf(0.f, 1.f - tv + v1)
                + fmaxf(0.f, 1.f - tv + v2) + fmaxf(0.f, 1.f - tv + v3);
        l += h * lp[k];
        t += expf(tv);
        d0 += expf(v0); d1 += expf(v1); d2 += expf(v2); d3 += expf(v3);
    }
    __shared__ float sh[6][256];
    sh[0][tid] = l; sh[1][tid] = t; sh[2][tid] = d0;
    sh[3][tid] = d1; sh[4][tid] = d2; sh[5][tid] = d3;
    __syncthreads();
    for (int s = 128; s > 0; s >>= 1) {
        if (tid < s)
            for (int q = 0; q < 6; q++) sh[q][tid] += sh[q][tid + s];
        __syncthreads();
    }
    if (tid == 0) {
        lsum[b] = sh[0][0];
        tp[b] = sh[1][0];
        dp[0 * B_ + b] = sh[2][0];
        dp[1 * B_ + b] = sh[3][0];
        dp[2 * B_ + b] = sh[4][0];
        dp[3 * B_ + b] = sh[5][0];
    }
}

__global__ void finalize(const float* __restrict__ lsum, const float* __restrict__ tp,
                         const float* __restrict__ dp, float* __restrict__ out) {
    int tid = threadIdx.x;
    float lo = 0.f, an = 0.f;
    for (int b = tid; b < B_; b += 256) {
        lo += lsum[b];
        float t = tp[b];
        bool ok = (t >= dp[0 * B_ + b]) && (t >= dp[1 * B_ + b]) &&
                  (t >= dp[2 * B_ + b]) && (t >= dp[3 * B_ + b]);
        an += ok ? 1.0f : 0.0f;
    }
    __shared__ float s0[256], s1[256];
    s0[tid] = lo; s1[tid] = an;
    __syncthreads();
    for (int s = 128; s > 0; s >>= 1) {
        if (tid < s) { s0[tid] += s0[tid + s]; s1[tid] += s1[tid + s]; }
        __syncthreads();
    }
    if (tid == 0) {
        out[0] = -s0[0] / ((float)B_ * (float)B_);
        out[1] = s1[0] / (float)B_;
    }
}

// ---------------- host orchestration ----------------
static inline dim3 gemm_grid(int M, int N) {
    return dim3((N + BN - 1) / BN, M / BM);
}

extern "C" void kernel_launch(void* const* d_in, const int* in_sizes, int n_in,
                              void* d_out, int out_size) {
    (void)in_sizes; (void)n_in; (void)out_size;
    const float* target      = (const float*)d_in[0];   // [B,F]
    const float* distractors = (const float*)d_in[1];   // [D,B,F]
    const int*   start_tok   = (const int*)d_in[2];
    // d_in[3] = max_sentence_length (compile-time L_=20)
    const float* emb_s   = (const float*)d_in[4];       // [V,E]
    const float* Wih_s   = (const float*)d_in[5];       // [4H,E]
    const float* Whh_s   = (const float*)d_in[6];       // [4H,H]
    const float* bih_s   = (const float*)d_in[7];
    const float* bhh_s   = (const float*)d_in[8];
    const float* aff_s_W = (const float*)d_in[9];       // [H,F]
    const float* aff_s_b = (const float*)d_in[10];      // [H]
    const float* probs_W = (const float*)d_in[11];      // [V,H]
    const float* probs_b = (const float*)d_in[12];      // [V]
    const float* emb_r   = (const float*)d_in[13];
    const float* Wih_r   = (const float*)d_in[14];
    const float* Whh_r   = (const float*)d_in[15];
    const float* bih_r   = (const float*)d_in[16];
    const float* bhh_r   = (const float*)d_in[17];
    const float* aff_r_W = (const float*)d_in[18];      // [F,H]
    const float* aff_r_b = (const float*)d_in[19];      // [F]
    float* out = (float*)d_out;

    // resolve scratch symbol addresses
    float *p_h, *p_c, *p_gates, *p_w, *p_logits, *p_logprob, *p_bias_s, *p_bias_r;
    float *p_r, *p_ts, *p_ds, *p_lsum, *p_tp, *p_dp;
    int *p_msg;
    cudaGetSymbolAddress((void**)&p_h, g_h);
    cudaGetSymbolAddress((void**)&p_c, g_c);
    cudaGetSymbolAddress((void**)&p_gates, g_gates);
    cudaGetSymbolAddress((void**)&p_w, g_w);
    cudaGetSymbolAddress((void**)&p_logits, g_logits);
    cudaGetSymbolAddress((void**)&p_msg, g_msg);
    cudaGetSymbolAddress((void**)&p_logprob, g_logprob);
    cudaGetSymbolAddress((void**)&p_bias_s, g_bias_s);
    cudaGetSymbolAddress((void**)&p_bias_r, g_bias_r);
    cudaGetSymbolAddress((void**)&p_r, g_r);
    cudaGetSymbolAddress((void**)&p_ts, g_ts);
    cudaGetSymbolAddress((void**)&p_ds, g_ds);
    cudaGetSymbolAddress((void**)&p_lsum, g_lsum);
    cudaGetSymbolAddress((void**)&p_tp, g_tp);
    cudaGetSymbolAddress((void**)&p_dp, g_dp);

    // combined LSTM biases
    add_vec<<<(G4H + 255) / 256, 256>>>(bih_s, bhh_s, p_bias_s, G4H);
    add_vec<<<(G4H + 255) / 256, 256>>>(bih_r, bhh_r, p_bias_r, G4H);

    // ---- Sender ----
    // h0 = target @ aff_s_W^T + aff_s_b ; c0 = 0
    gemm_nt<false, true><<<gemm_grid(B_, H_), 256>>>(target, aff_s_W, aff_s_b, p_h, B_, H_, F_);
    zero_kernel<<<(B_ * H_ + 255) / 256, 256>>>(p_c, B_ * H_);

    for (int s = 0; s < L_; s++) {
        if (s == 0) gather_start<<<B_, 128>>>(emb_s, start_tok, p_w);
        else        gather_tok<<<B_, 128>>>(emb_s, p_msg + (s - 1) * B_, p_w);

        gemm_nt<false, true><<<gemm_grid(B_, G4H), 256>>>(p_w, Wih_s, p_bias_s, p_gates, B_, G4H, E_);
        gemm_nt<true,  false><<<gemm_grid(B_, G4H), 256>>>(p_h, Whh_s, nullptr, p_gates, B_, G4H, H_);
        lstm_cell<<<(B_ * H_ + 255) / 256, 256>>>(p_gates, p_h, p_c);

        gemm_nt<false, true><<<gemm_grid(B_, V_), 256>>>(p_h, probs_W, probs_b, p_logits, B_, V_, H_);
        argmax_row<<<B_, 256>>>(p_logits, p_msg + s * B_, p_logprob, (s == L_ - 1) ? 1 : 0);
    }

    // ---- Receiver ----
    zero_kernel<<<(B_ * H_ + 255) / 256, 256>>>(p_h, B_ * H_);
    zero_kernel<<<(B_ * H_ + 255) / 256, 256>>>(p_c, B_ * H_);
    for (int s = 0; s < L_; s++) {
        gather_tok<<<B_, 128>>>(emb_r, p_msg + s * B_, p_w);
        gemm_nt<false, true><<<gemm_grid(B_, G4H), 256>>>(p_w, Wih_r, p_bias_r, p_gates, B_, G4H, E_);
        gemm_nt<true,  false><<<gemm_grid(B_, G4H), 256>>>(p_h, Whh_r, nullptr, p_gates, B_, G4H, H_);
        lstm_cell<<<(B_ * H_ + 255) / 256, 256>>>(p_gates, p_h, p_c);
    }

    // r = hr @ aff_r_W^T + aff_r_b
    gemm_nt<false, true><<<gemm_grid(B_, F_), 256>>>(p_h, aff_r_W, aff_r_b, p_r, B_, F_, H_);

    // ts = target @ r^T ; ds[d] = distractors[d] @ r^T
    gemm_nt<false, false><<<gemm_grid(B_, B_), 256>>>(target, p_r, nullptr, p_ts, B_, B_, F_);
    for (int d = 0; d < D_; d++)
        gemm_nt<false, false><<<gemm_grid(B_, B_), 256>>>(
            distractors + (size_t)d * B_ * F_, p_r, nullptr,
            p_ds + (size_t)d * B_ * B_, B_, B_, F_);

    // loss + accuracy
    reduce_rows<<<B_, 256>>>(p_ts, p_ds, p_logprob, p_lsum, p_tp, p_dp);
    finalize<<<1, 256>>>(p_lsum, p_tp, p_dp, out);
}

// round 3
// speedup vs baseline: 1.0013x; 1.0013x over previous
#include <cuda_runtime.h>
#include <math.h>
#include <stdint.h>

// Problem dims (fixed by the dataset generator)
#define B_  1024
#define F_  4096
#define V_  20000
#define E_  512
#define H_  1024
#define L_  20
#define D_  4
#define G4H 4096   // 4*H

// ---------------- scratch (no allocations allowed) ----------------
__device__ float g_h[B_*H_];
__device__ float g_c[B_*H_];
__device__ float g_gates[(size_t)B_*G4H];
__device__ float g_w[B_*E_];
__device__ float g_logits[(size_t)B_*V_];
__device__ int   g_msg[L_*B_];
__device__ float g_logprob[B_];
__device__ float g_bias_s[G4H];
__device__ float g_bias_r[G4H];
__device__ float g_r[(size_t)B_*F_];
__device__ float g_ts[(size_t)B_*B_];
__device__ float g_ds[(size_t)D_*B_*B_];
__device__ float g_lsum[B_];
__device__ float g_tp[B_];
__device__ float g_dp[D_*B_];

// ---------------- GEMM: C[M,N] (+)= A[M,K] @ B[N,K]^T (+ bias[N]) ----------------
// A row-major [M,K], Bm row-major [N,K] (both K-contiguous -> "NT" gemm).
// M must be a multiple of 128 (always 1024 here). N may have a tail. K % 16 == 0.
#define BM 128
#define BN 128
#define BKK 16

template<bool ACC, bool BIAS>
__global__ __launch_bounds__(256, 2)
void gemm_nt(const float* __restrict__ A, const float* __restrict__ Bm,
             const float* __restrict__ bias, float* __restrict__ C,
             int M, int N, int K)
{
    __shared__ float As[BKK][BM + 4];
    __shared__ float Bs[BKK][BN + 4];

    const int tid = threadIdx.x;
    const int tx = tid & 15;       // 0..15  -> N direction
    const int ty = tid >> 4;       // 0..15  -> M direction
    const int bm = blockIdx.y * BM;
    const int bn = blockIdx.x * BN;

    const int lrow = tid >> 2;         // 0..63
    const int lk4  = (tid & 3) * 4;    // 0,4,8,12

    float acc[8][8];
#pragma unroll
    for (int i = 0; i < 8; i++)
#pragma unroll
        for (int j = 0; j < 8; j++) acc[i][j] = 0.0f;

    for (int kt = 0; kt < K; kt += BKK) {
        // load A tile (M always in range)
#pragma unroll
        for (int r = 0; r < 2; r++) {
            int row = lrow + r * 64;
            float4 v = *(const float4*)&A[(size_t)(bm + row) * K + kt + lk4];
            As[lk4 + 0][row] = v.x; As[lk4 + 1][row] = v.y;
            As[lk4 + 2][row] = v.z; As[lk4 + 3][row] = v.w;
        }
        // load B tile (guard N tail)
#pragma unroll
        for (int r = 0; r < 2; r++) {
            int row = lrow + r * 64;
            int nrow = bn + row;
            float4 v = make_float4(0.f, 0.f, 0.f, 0.f);
            if (nrow < N) v = *(const float4*)&Bm[(size_t)nrow * K + kt + lk4];
            Bs[lk4 + 0][row] = v.x; Bs[lk4 + 1][row] = v.y;
            Bs[lk4 + 2][row] = v.z; Bs[lk4 + 3][row] = v.w;
        }
        __syncthreads();

#pragma unroll
        for (int k = 0; k < BKK; k++) {
            float a[8], b[8];
            *(float4*)&a[0] = *(const float4*)&As[k][ty * 8];
            *(float4*)&a[4] = *(const float4*)&As[k][ty * 8 + 4];
            *(float4*)&b[0] = *(const float4*)&Bs[k][tx * 8];
            *(float4*)&b[4] = *(const float4*)&Bs[k][tx * 8 + 4];
#pragma unroll
            for (int i = 0; i < 8; i++)
#pragma unroll
                for (int j = 0; j < 8; j++)
                    acc[i][j] = fmaf(a[i], b[j], acc[i][j]);
        }
        __syncthreads();
    }

    // epilogue
#pragma unroll
    for (int i = 0; i < 8; i++) {
        int m = bm + ty * 8 + i;
#pragma unroll
        for (int j = 0; j < 8; j++) {
            int n = bn + tx * 8 + j;
            if (n < N) {
                float v = acc[i][j];
                if (BIAS) v += bias[n];
                size_t off = (size_t)m * N + n;
                if (ACC) v += C[off];
                C[off] = v;
            }
        }
    }
}

// ---------------- small kernels ----------------
__global__ void zero_kernel(float* p, int n) {
    int i = blockIdx.x * blockDim.x + threadIdx.x;
    if (i < n) p[i] = 0.0f;
}

__global__ void add_vec(const float* a, const float* b, float* o, int n) {
    int i = blockIdx.x * blockDim.x + threadIdx.x;
    if (i < n) o[i] = a[i] + b[i];
}

// broadcast emb[*startp] to all rows
__global__ void gather_start(const float* __restrict__ emb, const int* __restrict__ startp,
                             float* __restrict__ out) {
    int s = *startp;
    int b = blockIdx.x;
    int e = threadIdx.x;  // 128 threads, E_/4 = 128 float4
    ((float4*)out)[(size_t)b * (E_ / 4) + e] =
        ((const float4*)emb)[(size_t)s * (E_ / 4) + e];
}

__global__ void gather_tok(const float* __restrict__ emb, const int* __restrict__ tok,
                           float* __restrict__ out) {
    int b = blockIdx.x;
    int t = tok[b];
    int e = threadIdx.x;
    ((float4*)out)[(size_t)b * (E_ / 4) + e] =
        ((const float4*)emb)[(size_t)t * (E_ / 4) + e];
}

__device__ __forceinline__ float sigf(float x) { return 1.0f / (1.0f + expf(-x)); }

// gates layout [B, 4H] chunks: i, f, g, o
__global__ void lstm_cell(const float* __restrict__ gates,
                          float* __restrict__ h, float* __restrict__ c) {
    int idx = blockIdx.x * blockDim.x + threadIdx.x;
    if (idx >= B_ * H_) return;
    int b = idx >> 10;            // /H_
    int j = idx & (H_ - 1);
    size_t base = (size_t)b * G4H;
    float gi = gates[base + j];
    float gf = gates[base + H_ + j];
    float gg = gates[base + 2 * H_ + j];
    float go = gates[base + 3 * H_ + j];
    float cn = sigf(gf) * c[idx] + sigf(gi) * tanhf(gg);
    c[idx] = cn;
    h[idx] = sigf(go) * tanhf(cn);
}

// per-row argmax over V (lowest index on ties = JAX semantics);
// if writeLp: logprob[b] = logits[amax] - logsumexp = -log(sum exp(x - max))
__global__ void argmax_row(const float* __restrict__ logits, int* __restrict__ msg,
                           float* __restrict__ logprob, int writeLp) {
    int b = blockIdx.x;
    const float* row = logits + (size_t)b * V_;
    int tid = threadIdx.x;

    float best = -3.4e38f;
    int bi = 0x7fffffff;
    for (int v = tid; v < V_; v += 256) {
        float x = row[v];
        if (x > best) { best = x; bi = v; }
    }
    __shared__ float sv[256];
    __shared__ int   si[256];
    sv[tid] = best; si[tid] = bi;
    __syncthreads();
    for (int s = 128; s > 0; s >>= 1) {
        if (tid < s) {
            if (sv[tid + s] > sv[tid] ||
                (sv[tid + s] == sv[tid] && si[tid + s] < si[tid])) {
                sv[tid] = sv[tid + s]; si[tid] = si[tid + s];
            }
        }
        __syncthreads();
    }
    float m = sv[0];
    int amax = si[0];
    if (tid == 0) msg[b] = amax;

    if (writeLp) {
        __syncthreads();
        float s = 0.0f;
        for (int v = tid; v < V_; v += 256) s += expf(row[v] - m);
        sv[tid] = s;
        __syncthreads();
        for (int st = 128; st > 0; st >>= 1) {
            if (tid < st) sv[tid] += sv[tid + st];
            __syncthreads();
        }
        if (tid == 0) logprob[b] = -logf(sv[0]);
    }
}

// per-row-b reductions over k: hinge*logprob sum, exp(ts) sum, exp(ds[d]) sums
__global__ void reduce_rows(const float* __restrict__ ts, const float* __restrict__ ds,
                            const float* __restrict__ lp,
                            float* __restrict__ lsum, float* __restrict__ tp,
                            float* __restrict__ dp) {
    int b = blockIdx.x;
    int tid = threadIdx.x;
    float l = 0.f, t = 0.f, d0 = 0.f, d1 = 0.f, d2 = 0.f, d3 = 0.f;
    for (int k = tid; k < B_; k += 256) {
        float tv = ts[(size_t)b * B_ + k];
        float v0 = ds[(size_t)0 * B_ * B_ + (size_t)b * B_ + k];
        float v1 = ds[(size_t)1 * B_ * B_ + (size_t)b * B_ + k];
        float v2 = ds[(size_t)2 * B_ * B_ + (size_t)b * B_ + k];
        float v3 = ds[(size_t)3 * B_ * B_ + (size_t)b * B_ + k];
        float h = fmaxf(0.f, 1.f - tv + v0) + fmaxf(0.f, 1.f - tv + v1)
                + fmaxf(0.f, 1.f - tv + v2) + fmaxf(0.f, 1.f - tv + v3);
        l += h * lp[k];
        t += expf(tv);
        d0 += expf(v0); d1 += expf(v1); d2 += expf(v2); d3 += expf(v3);
    }
    __shared__ float sh[6][256];
    sh[0][tid] = l; sh[1][tid] = t; sh[2][tid] = d0;
    sh[3][tid] = d1; sh[4][tid] = d2; sh[5][tid] = d3;
    __syncthreads();
    for (int s = 128; s > 0; s >>= 1) {
        if (tid < s)
            for (int q = 0; q < 6; q++) sh[q][tid] += sh[q][tid + s];
        __syncthreads();
    }
    if (tid == 0) {
        lsum[b] = sh[0][0];
        tp[b] = sh[1][0];
        dp[0 * B_ + b] = sh[2][0];
        dp[1 * B_ + b] = sh[3][0];
        dp[2 * B_ + b] = sh[4][0];
        dp[3 * B_ + b] = sh[5][0];
    }
}

__global__ void finalize(const float* __restrict__ lsum, const float* __restrict__ tp,
                         const float* __restrict__ dp, float* __restrict__ out) {
    int tid = threadIdx.x;
    float lo = 0.f, an = 0.f;
    for (int b = tid; b < B_; b += 256) {
        lo += lsum[b];
        float t = tp[b];
        bool ok = (t >= dp[0 * B_ + b]) && (t >= dp[1 * B_ + b]) &&
                  (t >= dp[2 * B_ + b]) && (t >= dp[3 * B_ + b]);
        an += ok ? 1.0f : 0.0f;
    }
    __shared__ float s0[256], s1[256];
    s0[tid] = lo; s1[tid] = an;
    __syncthreads();
    for (int s = 128; s > 0; s >>= 1) {
        if (tid < s) { s0[tid] += s0[tid + s]; s1[tid] += s1[tid + s]; }
        __syncthreads();
    }
    if (tid == 0) {
        out[0] = -s0[0] / ((float)B_ * (float)B_);
        out[1] = s1[0] / (float)B_;
    }
}

// ---------------- host orchestration ----------------
static inline dim3 gemm_grid(int M, int N) {
    return dim3((N + BN - 1) / BN, M / BM);
}

extern "C" void kernel_launch(void* const* d_in, const int* in_sizes, int n_in,
                              void* d_out, int out_size) {
    (void)in_sizes; (void)n_in; (void)out_size;
    const float* target      = (const float*)d_in[0];   // [B,F]
    const float* distractors = (const float*)d_in[1];   // [D,B,F]
    const int*   start_tok   = (const int*)d_in[2];
    // d_in[3] = max_sentence_length (compile-time L_=20)
    const float* emb_s   = (const float*)d_in[4];       // [V,E]
    const float* Wih_s   = (const float*)d_in[5];       // [4H,E]
    const float* Whh_s   = (const float*)d_in[6];       // [4H,H]
    const float* bih_s   = (const float*)d_in[7];
    const float* bhh_s   = (const float*)d_in[8];
    const float* aff_s_W = (const float*)d_in[9];       // [H,F]
    const float* aff_s_b = (const float*)d_in[10];      // [H]
    const float* probs_W = (const float*)d_in[11];      // [V,H]
    const float* probs_b = (const float*)d_in[12];      // [V]
    const float* emb_r   = (const float*)d_in[13];
    const float* Wih_r   = (const float*)d_in[14];
    const float* Whh_r   = (const float*)d_in[15];
    const float* bih_r   = (const float*)d_in[16];
    const float* bhh_r   = (const float*)d_in[17];
    const float* aff_r_W = (const float*)d_in[18];      // [F,H]
    const float* aff_r_b = (const float*)d_in[19];      // [F]
    float* out = (float*)d_out;

    // resolve scratch symbol addresses
    float *p_h, *p_c, *p_gates, *p_w, *p_logits, *p_logprob, *p_bias_s, *p_bias_r;
    float *p_r, *p_ts, *p_ds, *p_lsum, *p_tp, *p_dp;
    int *p_msg;
    cudaGetSymbolAddress((void**)&p_h, g_h);
    cudaGetSymbolAddress((void**)&p_c, g_c);
    cudaGetSymbolAddress((void**)&p_gates, g_gates);
    cudaGetSymbolAddress((void**)&p_w, g_w);
    cudaGetSymbolAddress((void**)&p_logits, g_logits);
    cudaGetSymbolAddress((void**)&p_msg, g_msg);
    cudaGetSymbolAddress((void**)&p_logprob, g_logprob);
    cudaGetSymbolAddress((void**)&p_bias_s, g_bias_s);
    cudaGetSymbolAddress((void**)&p_bias_r, g_bias_r);
    cudaGetSymbolAddress((void**)&p_r, g_r);
    cudaGetSymbolAddress((void**)&p_ts, g_ts);
    cudaGetSymbolAddress((void**)&p_ds, g_ds);
    cudaGetSymbolAddress((void**)&p_lsum, g_lsum);
    cudaGetSymbolAddress((void**)&p_tp, g_tp);
    cudaGetSymbolAddress((void**)&p_dp, g_dp);

    // combined LSTM biases
    add_vec<<<(G4H + 255) / 256, 256>>>(bih_s, bhh_s, p_bias_s, G4H);
    add_vec<<<(G4H + 255) / 256, 256>>>(bih_r, bhh_r, p_bias_r, G4H);

    // ---- Sender ----
    // h0 = target @ aff_s_W^T + aff_s_b ; c0 = 0
    gemm_nt<false, true><<<gemm_grid(B_, H_), 256>>>(target, aff_s_W, aff_s_b, p_h, B_, H_, F_);
    zero_kernel<<<(B_ * H_ + 255) / 256, 256>>>(p_c, B_ * H_);

    for (int s = 0; s < L_; s++) {
        if (s == 0) gather_start<<<B_, 128>>>(emb_s, start_tok, p_w);
        else        gather_tok<<<B_, 128>>>(emb_s, p_msg + (s - 1) * B_, p_w);

        gemm_nt<false, true><<<gemm_grid(B_, G4H), 256>>>(p_w, Wih_s, p_bias_s, p_gates, B_, G4H, E_);
        gemm_nt<true,  false><<<gemm_grid(B_, G4H), 256>>>(p_h, Whh_s, nullptr, p_gates, B_, G4H, H_);
        lstm_cell<<<(B_ * H_ + 255) / 256, 256>>>(p_gates, p_h, p_c);

        gemm_nt<false, true><<<gemm_grid(B_, V_), 256>>>(p_h, probs_W, probs_b, p_logits, B_, V_, H_);
        argmax_row<<<B_, 256>>>(p_logits, p_msg + s * B_, p_logprob, (s == L_ - 1) ? 1 : 0);
    }

    // ---- Receiver ----
    zero_kernel<<<(B_ * H_ + 255) / 256, 256>>>(p_h, B_ * H_);
    zero_kernel<<<(B_ * H_ + 255) / 256, 256>>>(p_c, B_ * H_);
    for (int s = 0; s < L_; s++) {
        gather_tok<<<B_, 128>>>(emb_r, p_msg + s * B_, p_w);
        gemm_nt<false, true><<<gemm_grid(B_, G4H), 256>>>(p_w, Wih_r, p_bias_r, p_gates, B_, G4H, E_);
        gemm_nt<true,  false><<<gemm_grid(B_, G4H), 256>>>(p_h, Whh_r, nullptr, p_gates, B_, G4H, H_);
        lstm_cell<<<(B_ * H_ + 255) / 256, 256>>>(p_gates, p_h, p_c);
    }

    // r = hr @ aff_r_W^T + aff_r_b
    gemm_nt<false, true><<<gemm_grid(B_, F_), 256>>>(p_h, aff_r_W, aff_r_b, p_r, B_, F_, H_);

    // ts = target @ r^T ; ds[d] = distractors[d] @ r^T
    gemm_nt<false, false><<<gemm_grid(B_, B_), 256>>>(target, p_r, nullptr, p_ts, B_, B_, F_);
    for (int d = 0; d < D_; d++)
        gemm_nt<false, false><<<gemm_grid(B_, B_), 256>>>(
            distractors + (size_t)d * B_ * F_, p_r, nullptr,
            p_ds + (size_t)d * B_ * B_, B_, B_, F_);

    // loss + accuracy
    reduce_rows<<<B_, 256>>>(p_ts, p_ds, p_logprob, p_lsum, p_tp, p_dp);
    finalize<<<1, 256>>>(p_lsum, p_tp, p_dp, out);
}

// round 5
// speedup vs baseline: 3.2787x; 3.2744x over previous
#include <cuda_runtime.h>
#include <cuda_bf16.h>
#include <math.h>
#include <stdint.h>

#define B_ 1024
#define F_ 4096
#define V_ 20000
#define NPAD 20096
#define E_ 512
#define H_ 1024
#define L_ 20
#define D_ 4
#define G4H 4096
#define KCAT 1536
#define KP_GATE (3*KCAT)   // 4608
#define KP_LOG  (3*H_)     // 3072
#define KP_TS   (3*F_)     // 12288

typedef __nv_bfloat16 bf16;

// ---------------- scratch (device globals; no runtime allocs) ----------------
__device__ __align__(256) bf16 d_probs[(size_t)NPAD*KP_LOG];
__device__ __align__(256) bf16 d_wcat_s[(size_t)G4H*KP_GATE];
__device__ __align__(256) bf16 d_wcat_r[(size_t)G4H*KP_GATE];
__device__ __align__(256) bf16 d_affs[(size_t)H_*KP_TS];
__device__ __align__(256) bf16 d_affr[(size_t)F_*KP_LOG];
__device__ __align__(256) bf16 d_a5[(size_t)5*B_*KP_TS];     // target + distractors, A-pattern
__device__ __align__(256) bf16 d_rdup[(size_t)B_*KP_TS];     // r, B-pattern
__device__ __align__(256) bf16 d_wact[(size_t)B_*KP_GATE];   // [emb|h] activation, A-pattern
__device__ __align__(256) bf16 d_hdup[(size_t)B_*KP_LOG];    // h, A-pattern

__device__ __align__(256) float g_hf[B_*H_];
__device__ __align__(256) float g_c[B_*H_];
__device__ __align__(256) float g_gates[(size_t)B_*G4H];
__device__ __align__(256) float g_logits[(size_t)B_*NPAD];
__device__ __align__(256) float g_rf[(size_t)B_*F_];
__device__ __align__(256) float g_sc[(size_t)5*B_*B_];       // [ts; ds0..ds3]
__device__ int   g_msg[L_*B_];
__device__ float g_logprob[B_];
__device__ float g_bias_s[G4H];
__device__ float g_bias_r[G4H];
__device__ float g_pbias[NPAD];
__device__ float g_lsum[B_];
__device__ float g_tp[B_];
__device__ float g_dp[D_*B_];

// ---------------- helpers ----------------
__device__ __forceinline__ uint32_t smem_u32(const void* p) {
    uint32_t a;
    asm("{ .reg .u64 t; cvta.to.shared.u64 t, %1; cvt.u32.u64 %0, t; }" : "=r"(a) : "l"(p));
    return a;
}
__device__ __forceinline__ void split2(float x, bf16& h, bf16& l) {
    h = __float2bfloat16(x);
    l = __float2bfloat16(x - __bfloat162float(h));
}

// ---------------- bf16 NT GEMM via mma.sync (HMMA) ----------------
// C[M,N] = A[M,Kp] @ B[N,Kp]^T (+bias). BM=BN=128, BK=64, 3-stage cp.async.
#define STAGE_BYTES 32768
#define SMEM_G (3*STAGE_BYTES)

__global__ void __launch_bounds__(256, 2)
gemm_bf16(const bf16* __restrict__ A, const bf16* __restrict__ Bw,
          const float* __restrict__ bias, int hasBias,
          float* __restrict__ C, int Kp, int Ncols, int swapRaster)
{
    extern __shared__ char smem_[];
    const uint32_t sbase = smem_u32(smem_);
    int bm, bn;
    if (swapRaster) { bm = blockIdx.y * 128; bn = blockIdx.x * 128; }
    else            { bm = blockIdx.x * 128; bn = blockIdx.y * 128; }
    const int tid = threadIdx.x, lane = tid & 31, wid = tid >> 5;
    const int wm = wid >> 2, wn = wid & 3;        // 2 x 4 warps

    const char* Ag = (const char*)(A + (size_t)bm * Kp);
    const char* Bg = (const char*)(Bw + (size_t)bn * Kp);
    const size_t rowB = (size_t)Kp * 2;
    const int nk = Kp >> 6;

    auto loadTile = [&](int ck, int st) {
        uint32_t sp = sbase + st * STAGE_BYTES;
        size_t ko = (size_t)ck * 128;          // 64 bf16 = 128 bytes
#pragma unroll
        for (int h = 0; h < 2; h++) {
            const char* G = (h ? Bg : Ag) + ko;
            uint32_t S = sp + h * 16384;
#pragma unroll
            for (int it = 0; it < 4; it++) {
                int r = it * 32 + (tid >> 3);
                int s = tid & 7;
                uint32_t sa = S + (uint32_t)r * 128 + ((s ^ (r & 7)) * 16);
                const char* ga = G + (size_t)r * rowB + s * 16;
                asm volatile("cp.async.cg.shared.global [%0], [%1], 16;" :: "r"(sa), "l"(ga));
            }
        }
        asm volatile("cp.async.commit_group;" ::: "memory");
    };

    float acc[4][4][4];
#pragma unroll
    for (int a = 0; a < 4; a++)
#pragma unroll
        for (int b = 0; b < 4; b++)
#pragma unroll
            for (int q = 0; q < 4; q++) acc[a][b][q] = 0.0f;

    loadTile(0, 0);
    if (nk > 1) loadTile(1, 1);

    for (int i = 0; i < nk; i++) {
        if (i + 1 < nk) asm volatile("cp.async.wait_group 1;" ::: "memory");
        else            asm volatile("cp.async.wait_group 0;" ::: "memory");
        __syncthreads();
        uint32_t Ab = sbase + (i % 3) * STAGE_BYTES;
        uint32_t Bb = Ab + 16384;
#pragma unroll
        for (int j = 0; j < 4; j++) {
            uint32_t af[4][4], bfr[2][4];
            int ar = lane & 15;
            int asel = 2 * j + (lane >> 4);
#pragma unroll
            for (int mi = 0; mi < 4; mi++) {
                int row = wm * 64 + mi * 16 + ar;
                uint32_t ad = Ab + row * 128 + ((asel ^ (row & 7)) * 16);
                asm volatile("ldmatrix.sync.aligned.m8n8.x4.shared.b16 {%0,%1,%2,%3}, [%4];"
                    : "=r"(af[mi][0]), "=r"(af[mi][1]), "=r"(af[mi][2]), "=r"(af[mi][3])
                    : "r"(ad));
            }
            int bsel = 2 * j + ((lane >> 3) & 1);
#pragma unroll
            for (int p = 0; p < 2; p++) {
                int nr = wn * 32 + (p * 2 + (lane >> 4)) * 8 + (lane & 7);
                uint32_t bd = Bb + nr * 128 + ((bsel ^ (nr & 7)) * 16);
                asm volatile("ldmatrix.sync.aligned.m8n8.x4.shared.b16 {%0,%1,%2,%3}, [%4];"
                    : "=r"(bfr[p][0]), "=r"(bfr[p][1]), "=r"(bfr[p][2]), "=r"(bfr[p][3])
                    : "r"(bd));
            }
#pragma unroll
            for (int mi = 0; mi < 4; mi++)
#pragma unroll
                for (int ni = 0; ni < 4; ni++) {
                    uint32_t b0 = bfr[ni >> 1][(ni & 1) * 2];
                    uint32_t b1 = bfr[ni >> 1][(ni & 1) * 2 + 1];
                    asm volatile(
                        "mma.sync.aligned.m16n8k16.row.col.f32.bf16.bf16.f32 "
                        "{%0,%1,%2,%3}, {%4,%5,%6,%7}, {%8,%9}, {%0,%1,%2,%3};"
                        : "+f"(acc[mi][ni][0]), "+f"(acc[mi][ni][1]),
                          "+f"(acc[mi][ni][2]), "+f"(acc[mi][ni][3])
                        : "r"(af[mi][0]), "r"(af[mi][1]), "r"(af[mi][2]), "r"(af[mi][3]),
                          "r"(b0), "r"(b1));
                }
        }
        if (i + 2 < nk) loadTile(i + 2, (i + 2) % 3);
    }

    // epilogue
#pragma unroll
    for (int mi = 0; mi < 4; mi++) {
        int row = bm + wm * 64 + mi * 16 + (lane >> 2);
#pragma unroll
        for (int ni = 0; ni < 4; ni++) {
            int col = bn + wn * 32 + ni * 8 + (lane & 3) * 2;
            float b0 = hasBias ? bias[col] : 0.0f;
            float b1 = hasBias ? bias[col + 1] : 0.0f;
            float2 v;
            v.x = acc[mi][ni][0] + b0; v.y = acc[mi][ni][1] + b1;
            *(float2*)&C[(size_t)row * Ncols + col] = v;
            v.x = acc[mi][ni][2] + b0; v.y = acc[mi][ni][3] + b1;
            *(float2*)&C[(size_t)(row + 8) * Ncols + col] = v;
        }
    }
}

// ---------------- split / prep kernels ----------------
// A-pattern: [hi, hi, lo]   B-pattern: [hi, lo, hi]
__global__ void split_dupA(const float* __restrict__ src, bf16* __restrict__ dst,
                           int K, size_t n) {
    size_t i = (size_t)blockIdx.x * blockDim.x + threadIdx.x;
    if (i >= n) return;
    size_t r = i / K, k = i % K;
    bf16 h, l; split2(src[i], h, l);
    size_t base = r * (size_t)(3 * K);
    dst[base + k] = h; dst[base + K + k] = h; dst[base + 2 * K + k] = l;
}

__global__ void split_dupB(const float* __restrict__ src, bf16* __restrict__ dst,
                           int K, size_t n) {
    size_t i = (size_t)blockIdx.x * blockDim.x + threadIdx.x;
    if (i >= n) return;
    size_t r = i / K, k = i % K;
    bf16 h, l; split2(src[i], h, l);
    size_t base = r * (size_t)(3 * K);
    dst[base + k] = h; dst[base + K + k] = l; dst[base + 2 * K + k] = h;
}

__global__ void split_dupB_pad(const float* __restrict__ src, bf16* __restrict__ dst,
                               int srcRows, int dstRows, int K) {
    size_t i = (size_t)blockIdx.x * blockDim.x + threadIdx.x;
    if (i >= (size_t)dstRows * K) return;
    size_t r = i / K, k = i % K;
    float x = (r < (size_t)srcRows) ? src[r * K + k] : 0.0f;
    bf16 h, l; split2(x, h, l);
    size_t base = r * (size_t)(3 * K);
    dst[base + k] = h; dst[base + K + k] = l; dst[base + 2 * K + k] = h;
}

__global__ void split_dupB_cat(const float* __restrict__ W1, const float* __restrict__ W2,
                               bf16* __restrict__ dst, int rows, int c1, int c2) {
    int K = c1 + c2;
    size_t i = (size_t)blockIdx.x * blockDim.x + threadIdx.x;
    if (i >= (size_t)rows * K) return;
    size_t r = i / K; int k = (int)(i % K);
    float x = (k < c1) ? W1[r * c1 + k] : W2[r * c2 + (k - c1)];
    bf16 h, l; split2(x, h, l);
    size_t base = r * (size_t)(3 * K);
    dst[base + k] = h; dst[base + K + k] = l; dst[base + 2 * K + k] = h;
}

__global__ void pad_bias(const float* __restrict__ src, float* __restrict__ dst) {
    int i = blockIdx.x * blockDim.x + threadIdx.x;
    if (i < NPAD) dst[i] = (i < V_) ? src[i] : -1e30f;
}

__global__ void add_vec(const float* a, const float* b, float* o, int n) {
    int i = blockIdx.x * blockDim.x + threadIdx.x;
    if (i < n) o[i] = a[i] + b[i];
}

__global__ void zero_f(float* p, size_t n) {
    size_t i = (size_t)blockIdx.x * blockDim.x + threadIdx.x;
    if (i < n) p[i] = 0.0f;
}

__global__ void zero_w(uint32_t* p, size_t n) {
    size_t i = (size_t)blockIdx.x * blockDim.x + threadIdx.x;
    if (i < n) p[i] = 0u;
}

// gather emb[token] -> wact emb-part (A-pattern over K=KCAT, cols [0,512))
__global__ void gather_split(const float* __restrict__ emb, const int* __restrict__ tok,
                             int isStart, bf16* __restrict__ wact) {
    int b = blockIdx.x;
    int t = isStart ? tok[0] : tok[b];
    size_t o = (size_t)b * KP_GATE;
    for (int c = threadIdx.x; c < E_; c += 128) {
        bf16 h, l; split2(emb[(size_t)t * E_ + c], h, l);
        wact[o + c] = h; wact[o + KCAT + c] = h; wact[o + 2 * KCAT + c] = l;
    }
}

__device__ __forceinline__ float sigf(float x) { return 1.0f / (1.0f + expf(-x)); }

__device__ __forceinline__ void store_h(float hv, int b, int j,
                                        bf16* hdup, bf16* wact) {
    bf16 h, l; split2(hv, h, l);
    size_t oh = (size_t)b * KP_LOG;
    hdup[oh + j] = h; hdup[oh + H_ + j] = h; hdup[oh + 2 * H_ + j] = l;
    size_t ow = (size_t)b * KP_GATE + E_;
    wact[ow + j] = h; wact[ow + KCAT + j] = h; wact[ow + 2 * KCAT + j] = l;
}

__global__ void lstm_split(const float* __restrict__ gates, float* __restrict__ c,
                           bf16* __restrict__ hdup, bf16* __restrict__ wact) {
    int idx = blockIdx.x * blockDim.x + threadIdx.x;
    if (idx >= B_ * H_) return;
    int b = idx >> 10, j = idx & (H_ - 1);
    size_t base = (size_t)b * G4H;
    float gi = gates[base + j], gf = gates[base + H_ + j];
    float gg = gates[base + 2 * H_ + j], go = gates[base + 3 * H_ + j];
    float cn = sigf(gf) * c[idx] + sigf(gi) * tanhf(gg);
    c[idx] = cn;
    store_h(sigf(go) * tanhf(cn), b, j, hdup, wact);
}

__global__ void hsplit_wact(const float* __restrict__ src,
                            bf16* __restrict__ hdup, bf16* __restrict__ wact) {
    int idx = blockIdx.x * blockDim.x + threadIdx.x;
    if (idx >= B_ * H_) return;
    store_h(src[idx], idx >> 10, idx & (H_ - 1), hdup, wact);
}

__global__ void rsplit(const float* __restrict__ src, bf16* __restrict__ dst) {
    int idx = blockIdx.x * blockDim.x + threadIdx.x;
    if (idx >= B_ * F_) return;
    int b = idx >> 12, k = idx & (F_ - 1);
    bf16 h, l; split2(src[idx], h, l);
    size_t base = (size_t)b * KP_TS;
    dst[base + k] = h; dst[base + F_ + k] = l; dst[base + 2 * F_ + k] = h;
}

// argmax over rows of g_logits [B, NPAD] limited to V_
__global__ void argmax_row(const float* __restrict__ logits, int* __restrict__ msg,
                           float* __restrict__ logprob, int writeLp) {
    int b = blockIdx.x;
    const float* row = logits + (size_t)b * NPAD;
    int tid = threadIdx.x;
    float best = -3.4e38f; int bi = 0x7fffffff;
    for (int v = tid; v < V_; v += 256) {
        float x = row[v];
        if (x > best) { best = x; bi = v; }
    }
    __shared__ float sv[256];
    __shared__ int   si[256];
    sv[tid] = best; si[tid] = bi;
    __syncthreads();
    for (int s = 128; s > 0; s >>= 1) {
        if (tid < s) {
            if (sv[tid + s] > sv[tid] ||
                (sv[tid + s] == sv[tid] && si[tid + s] < si[tid])) {
                sv[tid] = sv[tid + s]; si[tid] = si[tid + s];
            }
        }
        __syncthreads();
    }
    float m = sv[0];
    if (tid == 0) msg[b] = si[0];
    if (writeLp) {
        __syncthreads();
        float s = 0.0f;
        for (int v = tid; v < V_; v += 256) s += expf(row[v] - m);
        sv[tid] = s;
        __syncthreads();
        for (int st = 128; st > 0; st >>= 1) {
            if (tid < st) sv[tid] += sv[tid + st];
            __syncthreads();
        }
        if (tid == 0) logprob[b] = -logf(sv[0]);
    }
}

// sc layout: rows 0..1023 = ts[b][k]; rows 1024+d*1024+b = ds[d][b][k]
__global__ void reduce_rows(const float* __restrict__ sc, const float* __restrict__ lp,
                            float* __restrict__ lsum, float* __restrict__ tp,
                            float* __restrict__ dp) {
    int b = blockIdx.x, tid = threadIdx.x;
    float l = 0.f, t = 0.f, d0 = 0.f, d1 = 0.f, d2 = 0.f, d3 = 0.f;
    const float* tsr = sc + (size_t)b * B_;
    const float* dr0 = sc + (size_t)(1024 + b) * B_;
    const float* dr1 = sc + (size_t)(2048 + b) * B_;
    const float* dr2 = sc + (size_t)(3072 + b) * B_;
    const float* dr3 = sc + (size_t)(4096 + b) * B_;
    for (int k = tid; k < B_; k += 256) {
        float tv = tsr[k];
        float v0 = dr0[k], v1 = dr1[k], v2 = dr2[k], v3 = dr3[k];
        float h = fmaxf(0.f, 1.f - tv + v0) + fmaxf(0.f, 1.f - tv + v1)
                + fmaxf(0.f, 1.f - tv + v2) + fmaxf(0.f, 1.f - tv + v3);
        l += h * lp[k];
        t += expf(tv);
        d0 += expf(v0); d1 += expf(v1); d2 += expf(v2); d3 += expf(v3);
    }
    __shared__ float sh[6][256];
    sh[0][tid] = l; sh[1][tid] = t; sh[2][tid] = d0;
    sh[3][tid] = d1; sh[4][tid] = d2; sh[5][tid] = d3;
    __syncthreads();
    for (int s = 128; s > 0; s >>= 1) {
        if (tid < s)
            for (int q = 0; q < 6; q++) sh[q][tid] += sh[q][tid + s];
        __syncthreads();
    }
    if (tid == 0) {
        lsum[b] = sh[0][0]; tp[b] = sh[1][0];
        dp[b] = sh[2][0]; dp[B_ + b] = sh[3][0];
        dp[2 * B_ + b] = sh[4][0]; dp[3 * B_ + b] = sh[5][0];
    }
}

__global__ void finalize(const float* __restrict__ lsum, const float* __restrict__ tp,
                         const float* __restrict__ dp, float* __restrict__ out) {
    int tid = threadIdx.x;
    float lo = 0.f, an = 0.f;
    for (int b = tid; b < B_; b += 256) {
        lo += lsum[b];
        float t = tp[b];
        bool ok = (t >= dp[b]) && (t >= dp[B_ + b]) &&
                  (t >= dp[2 * B_ + b]) && (t >= dp[3 * B_ + b]);
        an += ok ? 1.0f : 0.0f;
    }
    __shared__ float s0[256], s1[256];
    s0[tid] = lo; s1[tid] = an;
    __syncthreads();
    for (int s = 128; s > 0; s >>= 1) {
        if (tid < s) { s0[tid] += s0[tid + s]; s1[tid] += s1[tid + s]; }
        __syncthreads();
    }
    if (tid == 0) {
        out[0] = -s0[0] / ((float)B_ * (float)B_);
        out[1] = s1[0] / (float)B_;
    }
}

// ---------------- host ----------------
#define SYM(p, g) cudaGetSymbolAddress((void**)&p, g)
static inline size_t gb1(size_t n) { return (n + 255) / 256; }

extern "C" void kernel_launch(void* const* d_in, const int* in_sizes, int n_in,
                              void* d_out, int out_size) {
    (void)in_sizes; (void)n_in; (void)out_size;
    const float* target      = (const float*)d_in[0];
    const float* distractors = (const float*)d_in[1];
    const int*   start_tok   = (const int*)d_in[2];
    const float* emb_s   = (const float*)d_in[4];
    const float* Wih_s   = (const float*)d_in[5];
    const float* Whh_s   = (const float*)d_in[6];
    const float* bih_s   = (const float*)d_in[7];
    const float* bhh_s   = (const float*)d_in[8];
    const float* aff_s_W = (const float*)d_in[9];
    const float* aff_s_b = (const float*)d_in[10];
    const float* probs_W = (const float*)d_in[11];
    const float* probs_b = (const float*)d_in[12];
    const float* emb_r   = (const float*)d_in[13];
    const float* Wih_r   = (const float*)d_in[14];
    const float* Whh_r   = (const float*)d_in[15];
    const float* bih_r   = (const float*)d_in[16];
    const float* bhh_r   = (const float*)d_in[17];
    const float* aff_r_W = (const float*)d_in[18];
    const float* aff_r_b = (const float*)d_in[19];
    float* out = (float*)d_out;

    bf16 *pProbs, *pWcS, *pWcR, *pAfS, *pAfR, *pA5, *pRd, *pWa, *pHd;
    float *pHf, *pC, *pG, *pLg, *pRf, *pSc, *pLp, *pBs, *pBr, *pPb, *pLs, *pTp, *pDp;
    int *pMsg;
    SYM(pProbs, d_probs); SYM(pWcS, d_wcat_s); SYM(pWcR, d_wcat_r);
    SYM(pAfS, d_affs); SYM(pAfR, d_affr); SYM(pA5, d_a5); SYM(pRd, d_rdup);
    SYM(pWa, d_wact); SYM(pHd, d_hdup);
    SYM(pHf, g_hf); SYM(pC, g_c); SYM(pG, g_gates); SYM(pLg, g_logits);
    SYM(pRf, g_rf); SYM(pSc, g_sc); SYM(pLp, g_logprob);
    SYM(pBs, g_bias_s); SYM(pBr, g_bias_r); SYM(pPb, g_pbias);
    SYM(pLs, g_lsum); SYM(pTp, g_tp); SYM(pDp, g_dp); SYM(pMsg, g_msg);

    cudaFuncSetAttribute(gemm_bf16, cudaFuncAttributeMaxDynamicSharedMemorySize, SMEM_G);

    // ---- prep ----
    add_vec<<<(G4H + 255) / 256, 256>>>(bih_s, bhh_s, pBs, G4H);
    add_vec<<<(G4H + 255) / 256, 256>>>(bih_r, bhh_r, pBr, G4H);
    pad_bias<<<(NPAD + 255) / 256, 256>>>(probs_b, pPb);
    split_dupA<<<gb1((size_t)B_ * F_), 256>>>(target, pA5, F_, (size_t)B_ * F_);
    split_dupA<<<gb1((size_t)D_ * B_ * F_), 256>>>(distractors, pA5 + (size_t)B_ * KP_TS,
                                                   F_, (size_t)D_ * B_ * F_);
    split_dupB<<<gb1((size_t)H_ * F_), 256>>>(aff_s_W, pAfS, F_, (size_t)H_ * F_);
    split_dupB<<<gb1((size_t)F_ * H_), 256>>>(aff_r_W, pAfR, H_, (size_t)F_ * H_);
    split_dupB_pad<<<gb1((size_t)NPAD * H_), 256>>>(probs_W, pProbs, V_, NPAD, H_);
    split_dupB_cat<<<gb1((size_t)G4H * KCAT), 256>>>(Wih_s, Whh_s, pWcS, G4H, E_, H_);
    split_dupB_cat<<<gb1((size_t)G4H * KCAT), 256>>>(Wih_r, Whh_r, pWcR, G4H, E_, H_);

    // ---- sender init ----
    zero_f<<<gb1((size_t)B_ * H_), 256>>>(pC, (size_t)B_ * H_);
    gemm_bf16<<<dim3(8, 8), 256, SMEM_G>>>(pA5, pAfS, aff_s_b, 1, pHf, KP_TS, H_, 0);
    hsplit_wact<<<gb1((size_t)B_ * H_), 256>>>(pHf, pHd, pWa);

    for (int s = 0; s < L_; s++) {
        gather_split<<<B_, 128>>>(emb_s, s == 0 ? start_tok : pMsg + (s - 1) * B_,
                                  s == 0 ? 1 : 0, pWa);
        gemm_bf16<<<dim3(8, 32), 256, SMEM_G>>>(pWa, pWcS, pBs, 1, pG, KP_GATE, G4H, 0);
        lstm_split<<<gb1((size_t)B_ * H_), 256>>>(pG, pC, pHd, pWa);
        gemm_bf16<<<dim3(8, 157), 256, SMEM_G>>>(pHd, pProbs, pPb, 1, pLg, KP_LOG, NPAD, 0);
        argmax_row<<<B_, 256>>>(pLg, pMsg + s * B_, pLp, (s == L_ - 1) ? 1 : 0);
    }

    // ---- receiver ----
    zero_f<<<gb1((size_t)B_ * H_), 256>>>(pC, (size_t)B_ * H_);
    zero_w<<<gb1((size_t)B_ * KP_GATE / 2), 256>>>((uint32_t*)pWa, (size_t)B_ * KP_GATE / 2);
    for (int s = 0; s < L_; s++) {
        gather_split<<<B_, 128>>>(emb_r, pMsg + s * B_, 0, pWa);
        gemm_bf16<<<dim3(8, 32), 256, SMEM_G>>>(pWa, pWcR, pBr, 1, pG, KP_GATE, G4H, 0);
        lstm_split<<<gb1((size_t)B_ * H_), 256>>>(pG, pC, pHd, pWa);
    }

    // ---- r, ts/ds, loss ----
    gemm_bf16<<<dim3(8, 32), 256, SMEM_G>>>(pHd, pAfR, aff_r_b, 1, pRf, KP_LOG, F_, 0);
    rsplit<<<gb1((size_t)B_ * F_), 256>>>(pRf, pRd);
    gemm_bf16<<<dim3(8, 40), 256, SMEM_G>>>(pA5, pRd, nullptr, 0, pSc, KP_TS, B_, 1);
    reduce_rows<<<B_, 256>>>(pSc, pLp, pLs, pTp, pDp);
    finalize<<<1, 256>>>(pLs, pTp, pDp, out);
}